// round 4
// baseline (speedup 1.0000x reference)
#include <cuda_runtime.h>
#include <math.h>

// Chamfer distance loss. B=b*s batches (16), N=4096 points, D=3.
//   loss = (sum of all 2*B*N nearest-neighbor distances) / (B*N)
//
// min_j sqrt(d2) = sqrt(max(min_j (|t_j|^2 - 2 p.t_j) + |p|^2, 0)).
// Inner loop per warp-j: 2 LDS.128 + 6 fma.rn.f32x2 + 4 FMNMX for 128 pairs
// (fma-pipe bound, ~85K cyc chip-wide). Two directions via gridDim.z;
// column-split x4 for single-wave balance; each split writes its partial
// row-min to a private slot (no atomics, no init pass).

#define N_PTS           4096
#define THREADS         128
#define RT              4                        // rows per thread (2 packed pairs)
#define ROWS_PER_BLOCK  (THREADS * RT)           // 512
#define STRIPS          (N_PTS / ROWS_PER_BLOCK) // 8
#define CS              4                        // column splits
#define COLS_PER_BLOCK  (N_PTS / CS)             // 1024
#define MAX_B           32

__device__ float g_pmin[CS * 2 * MAX_B * N_PTS]; // partial min d2 per split
__device__ float g_partial[256];

typedef unsigned long long ull;

static __device__ __forceinline__ ull dup2(float f) {
    ull r; asm("mov.b64 %0, {%1, %1};" : "=l"(r) : "f"(f)); return r;
}
static __device__ __forceinline__ ull pack2(float lo, float hi) {
    ull r; asm("mov.b64 %0, {%1, %2};" : "=l"(r) : "f"(lo), "f"(hi)); return r;
}
static __device__ __forceinline__ void unpack2(ull v, float& lo, float& hi) {
    asm("mov.b64 {%0, %1}, %2;" : "=f"(lo), "=f"(hi) : "l"(v));
}
static __device__ __forceinline__ ull fma2(ull a, ull b, ull c) {
    ull d; asm("fma.rn.f32x2 %0, %1, %2, %3;" : "=l"(d) : "l"(a), "l"(b), "l"(c));
    return d;
}

__global__ __launch_bounds__(THREADS)
void nn_min_kernel(const float* __restrict__ pred, const float* __restrict__ targ) {
    // Per target column j, duplicated-pair layout for packed-f32x2 operands:
    //   sY[2j]   = { dup(-2*ty0), dup(-2*ty1) }
    //   sY[2j+1] = { dup(-2*ty2), dup(|t|^2)  }
    __shared__ ulonglong2 sY[COLS_PER_BLOCK * 2];   // 32 KB

    const int strip = blockIdx.x;
    const int batch = blockIdx.y;
    const int dir   = blockIdx.z & 1;
    const int csp   = blockIdx.z >> 1;
    const int tid   = threadIdx.x;
    const int B     = gridDim.y;

    const float* X = dir ? targ : pred;   // query rows
    const float* Y = dir ? pred : targ;   // database cols
    X += (size_t)batch * N_PTS * 3;
    Y += (size_t)batch * N_PTS * 3;

    // This thread's 4 query rows: 12 consecutive floats, 16B-aligned.
    // Issued first so the LDG latency overlaps the tile-fill loop.
    const int row0 = strip * ROWS_PER_BLOCK + tid * RT;
    const float4* xp = (const float4*)(X + (size_t)row0 * 3);
    const float4 v0 = __ldg(xp + 0);
    const float4 v1 = __ldg(xp + 1);
    const float4 v2 = __ldg(xp + 2);

    // Fill the target tile for this column chunk.
    const int j0 = csp * COLS_PER_BLOCK;
#pragma unroll 4
    for (int j = tid; j < COLS_PER_BLOCK; j += THREADS) {
        const float* yp = Y + (size_t)(j0 + j) * 3;
        float t0 = __ldg(yp + 0), t1 = __ldg(yp + 1), t2 = __ldg(yp + 2);
        float c = t0 * t0 + t1 * t1 + t2 * t2;
        ulonglong2 q0, q1;
        q0.x = dup2(-2.0f * t0);
        q0.y = dup2(-2.0f * t1);
        q1.x = dup2(-2.0f * t2);
        q1.y = dup2(c);
        sY[2 * j]     = q0;
        sY[2 * j + 1] = q1;
    }

    // r0=(v0.x,v0.y,v0.z) r1=(v0.w,v1.x,v1.y) r2=(v1.z,v1.w,v2.x) r3=(v2.y,v2.z,v2.w)
    const ull px01 = pack2(v0.x, v0.w), py01 = pack2(v0.y, v1.x), pz01 = pack2(v0.z, v1.y);
    const ull px23 = pack2(v1.z, v2.y), py23 = pack2(v1.w, v2.z), pz23 = pack2(v2.x, v2.w);
    const float a0 = v0.x * v0.x + v0.y * v0.y + v0.z * v0.z;
    const float a1 = v0.w * v0.w + v1.x * v1.x + v1.y * v1.y;
    const float a2 = v1.z * v1.z + v1.w * v1.w + v2.x * v2.x;
    const float a3 = v2.y * v2.y + v2.z * v2.z + v2.w * v2.w;

    __syncthreads();

    float m0 = 3.402823466e+38f, m1 = m0, m2 = m0, m3 = m0;

#pragma unroll 8
    for (int j = 0; j < COLS_PER_BLOCK; ++j) {
        const ulonglong2 q0 = sY[2 * j];
        const ulonglong2 q1 = sY[2 * j + 1];
        // h = c - 2*p.t  (|p|^2 is a per-row constant; added after the loop)
        ull hA = fma2(px01, q0.x, fma2(py01, q0.y, fma2(pz01, q1.x, q1.y)));
        ull hB = fma2(px23, q0.x, fma2(py23, q0.y, fma2(pz23, q1.x, q1.y)));
        float h0, h1, h2, h3;
        unpack2(hA, h0, h1);
        unpack2(hB, h2, h3);
        m0 = fminf(m0, h0);
        m1 = fminf(m1, h1);
        m2 = fminf(m2, h2);
        m3 = fminf(m3, h3);
    }

    // Partial min d2 for this column split (clamped >= 0); one STG.128.
    float4 d;
    d.x = fmaxf(a0 + m0, 0.0f);
    d.y = fmaxf(a1 + m1, 0.0f);
    d.z = fmaxf(a2 + m2, 0.0f);
    d.w = fmaxf(a3 + m3, 0.0f);
    size_t slot = ((size_t)csp * 2 * B + (size_t)dir * B + batch) * N_PTS + row0;
    *(float4*)&g_pmin[slot] = d;
}

// Stage 1: min across the CS column splits, sqrt, partial sums.
// Spread over 128 blocks (MUFU sqrt at ~0.5/cyc/SM would bind on one block).
__global__ void reduce1_kernel(int n) {   // n = 2*B*N rows
    __shared__ float red[256];
    int chunk = (n + gridDim.x - 1) / gridDim.x;
    int base = blockIdx.x * chunk;
    int end = min(base + chunk, n);
    float s = 0.0f;
    for (int i = base + threadIdx.x; i < end; i += 256) {
        float m = g_pmin[i];
        m = fminf(m, g_pmin[n + i]);
        m = fminf(m, g_pmin[2 * n + i]);
        m = fminf(m, g_pmin[3 * n + i]);
        s += sqrtf(m);
    }
    red[threadIdx.x] = s;
    __syncthreads();
    for (int o = 128; o > 0; o >>= 1) {
        if (threadIdx.x < o) red[threadIdx.x] += red[threadIdx.x + o];
        __syncthreads();
    }
    if (threadIdx.x == 0) g_partial[blockIdx.x] = red[0];
}

__global__ void reduce2_kernel(float* __restrict__ out, int nblocks, float scale) {
    __shared__ float red[128];
    float s = 0.0f;
    for (int i = threadIdx.x; i < nblocks; i += 128) s += g_partial[i];
    red[threadIdx.x] = s;
    __syncthreads();
    for (int o = 64; o > 0; o >>= 1) {
        if (threadIdx.x < o) red[threadIdx.x] += red[threadIdx.x + o];
        __syncthreads();
    }
    if (threadIdx.x == 0) out[0] = red[0] * scale;
}

extern "C" void kernel_launch(void* const* d_in, const int* in_sizes, int n_in,
                              void* d_out, int out_size) {
    const float* pred = (const float*)d_in[0];
    const float* targ = (const float*)d_in[1];
    int B = in_sizes[0] / (N_PTS * 3);              // b*s = 16

    dim3 grid(STRIPS, B, 2 * CS);                    // 8 x 16 x 8 = 1024 blocks
    nn_min_kernel<<<grid, THREADS>>>(pred, targ);

    int nrows = 2 * B * N_PTS;                       // 131072
    reduce1_kernel<<<128, 256>>>(nrows);
    reduce2_kernel<<<1, 128>>>((float*)d_out, 128, 1.0f / ((float)B * (float)N_PTS));
}

// round 14
// speedup vs baseline: 1.0403x; 1.0403x over previous
#include <cuda_runtime.h>
#include <math.h>

// Chamfer distance loss. B=b*s batches (16), N=4096 points, D=3.
//   loss = (sum of all 2*B*N nearest-neighbor distances) / (B*N)
//
// min_j sqrt(d2) = sqrt(max(min_j (|t_j|^2 - 2 p.t_j) + |p|^2, 0)).
// Inner loop per warp-j: 2 LDS.128 (broadcast) + 6 fma.rn.f32x2 + 4 FMNMX
// covering 128 (row,col) pairs. Chip issue floor ~87K cyc.
//
// R4 measured: regs=78 -> 6 blocks/SM, 24 warps, occ 26.9%, issue 44%.
// This candidate: CS=8 -> 16KB tiles, 2048 equal blocks (13-14 per SM,
// perfect-balance + work-steal => packing insensitive to regs/blocks-per-SM),
// and __launch_bounds__(128,8) (64-reg cap) -> 8 blocks/SM = 32 warps resident.

#define N_PTS           4096
#define THREADS         128
#define RT              4                        // rows per thread (2 packed pairs)
#define ROWS_PER_BLOCK  (THREADS * RT)           // 512
#define STRIPS          (N_PTS / ROWS_PER_BLOCK) // 8
#define CS              8                        // column splits
#define COLS_PER_BLOCK  (N_PTS / CS)             // 512
#define MAX_B           32

__device__ float g_pmin[CS * 2 * MAX_B * N_PTS]; // partial min d2 per split
__device__ float g_partial[256];

typedef unsigned long long ull;

static __device__ __forceinline__ ull dup2(float f) {
    ull r; asm("mov.b64 %0, {%1, %1};" : "=l"(r) : "f"(f)); return r;
}
static __device__ __forceinline__ ull pack2(float lo, float hi) {
    ull r; asm("mov.b64 %0, {%1, %2};" : "=l"(r) : "f"(lo), "f"(hi)); return r;
}
static __device__ __forceinline__ void unpack2(ull v, float& lo, float& hi) {
    asm("mov.b64 {%0, %1}, %2;" : "=f"(lo), "=f"(hi) : "l"(v));
}
static __device__ __forceinline__ ull fma2(ull a, ull b, ull c) {
    ull d; asm("fma.rn.f32x2 %0, %1, %2, %3;" : "=l"(d) : "l"(a), "l"(b), "l"(c));
    return d;
}

__global__ __launch_bounds__(THREADS, 8)   // <= 64 regs: 8 blocks/SM, 32 warps
void nn_min_kernel(const float* __restrict__ pred, const float* __restrict__ targ) {
    // Per target column j, duplicated-pair layout for packed-f32x2 operands:
    //   sY[2j]   = { dup(-2*ty0), dup(-2*ty1) }
    //   sY[2j+1] = { dup(-2*ty2), dup(|t|^2)  }
    __shared__ ulonglong2 sY[COLS_PER_BLOCK * 2];   // 16 KB

    const int strip = blockIdx.x;
    const int batch = blockIdx.y;
    const int dir   = blockIdx.z & 1;
    const int csp   = blockIdx.z >> 1;
    const int tid   = threadIdx.x;
    const int B     = gridDim.y;

    const float* X = dir ? targ : pred;   // query rows
    const float* Y = dir ? pred : targ;   // database cols
    X += (size_t)batch * N_PTS * 3;
    Y += (size_t)batch * N_PTS * 3;

    // This thread's 4 query rows: 12 consecutive floats, 16B-aligned.
    // Issued first so the LDG latency overlaps the tile-fill loop.
    const int row0 = strip * ROWS_PER_BLOCK + tid * RT;
    const float4* xp = (const float4*)(X + (size_t)row0 * 3);
    const float4 v0 = __ldg(xp + 0);
    const float4 v1 = __ldg(xp + 1);
    const float4 v2 = __ldg(xp + 2);

    // Fill the target tile for this column chunk (512 cols / 128 thr = 4 its).
    const int j0 = csp * COLS_PER_BLOCK;
#pragma unroll 4
    for (int j = tid; j < COLS_PER_BLOCK; j += THREADS) {
        const float* yp = Y + (size_t)(j0 + j) * 3;
        float t0 = __ldg(yp + 0), t1 = __ldg(yp + 1), t2 = __ldg(yp + 2);
        float c = t0 * t0 + t1 * t1 + t2 * t2;
        ulonglong2 q0, q1;
        q0.x = dup2(-2.0f * t0);
        q0.y = dup2(-2.0f * t1);
        q1.x = dup2(-2.0f * t2);
        q1.y = dup2(c);
        sY[2 * j]     = q0;
        sY[2 * j + 1] = q1;
    }

    // r0=(v0.x,v0.y,v0.z) r1=(v0.w,v1.x,v1.y) r2=(v1.z,v1.w,v2.x) r3=(v2.y,v2.z,v2.w)
    const ull px01 = pack2(v0.x, v0.w), py01 = pack2(v0.y, v1.x), pz01 = pack2(v0.z, v1.y);
    const ull px23 = pack2(v1.z, v2.y), py23 = pack2(v1.w, v2.z), pz23 = pack2(v2.x, v2.w);

    __syncthreads();

    float m0 = 3.402823466e+38f, m1 = m0, m2 = m0, m3 = m0;

#pragma unroll 8
    for (int j = 0; j < COLS_PER_BLOCK; ++j) {
        const ulonglong2 q0 = sY[2 * j];
        const ulonglong2 q1 = sY[2 * j + 1];
        // h = c - 2*p.t  (|p|^2 is a per-row constant; added after the loop)
        ull hA = fma2(px01, q0.x, fma2(py01, q0.y, fma2(pz01, q1.x, q1.y)));
        ull hB = fma2(px23, q0.x, fma2(py23, q0.y, fma2(pz23, q1.x, q1.y)));
        float h0, h1, h2, h3;
        unpack2(hA, h0, h1);
        unpack2(hB, h2, h3);
        m0 = fminf(m0, h0);
        m1 = fminf(m1, h1);
        m2 = fminf(m2, h2);
        m3 = fminf(m3, h3);
    }

    // Recompute |p|^2 from the packed registers (post-loop; keeps live-range
    // across the hot loop minimal). unpack MOVs alias away in SASS.
    float x0, x1, x2, x3, y0, y1, y2, y3, z0, z1, z2, z3;
    unpack2(px01, x0, x1); unpack2(px23, x2, x3);
    unpack2(py01, y0, y1); unpack2(py23, y2, y3);
    unpack2(pz01, z0, z1); unpack2(pz23, z2, z3);
    const float a0 = x0 * x0 + y0 * y0 + z0 * z0;
    const float a1 = x1 * x1 + y1 * y1 + z1 * z1;
    const float a2 = x2 * x2 + y2 * y2 + z2 * z2;
    const float a3 = x3 * x3 + y3 * y3 + z3 * z3;

    // Partial min d2 for this column split (clamped >= 0); one STG.128.
    float4 d;
    d.x = fmaxf(a0 + m0, 0.0f);
    d.y = fmaxf(a1 + m1, 0.0f);
    d.z = fmaxf(a2 + m2, 0.0f);
    d.w = fmaxf(a3 + m3, 0.0f);
    size_t slot = ((size_t)csp * 2 * B + (size_t)dir * B + batch) * N_PTS + row0;
    *(float4*)&g_pmin[slot] = d;
}

// Stage 1: min across the CS column splits, sqrt, partial sums.
// Spread over 128 blocks (MUFU sqrt would bind on a single block).
__global__ void reduce1_kernel(int n) {   // n = 2*B*N rows
    __shared__ float red[256];
    int chunk = (n + gridDim.x - 1) / gridDim.x;
    int base = blockIdx.x * chunk;
    int end = min(base + chunk, n);
    float s = 0.0f;
    for (int i = base + threadIdx.x; i < end; i += 256) {
        float m = g_pmin[i];
#pragma unroll
        for (int k = 1; k < CS; ++k)
            m = fminf(m, g_pmin[(size_t)k * n + i]);
        s += sqrtf(m);
    }
    red[threadIdx.x] = s;
    __syncthreads();
    for (int o = 128; o > 0; o >>= 1) {
        if (threadIdx.x < o) red[threadIdx.x] += red[threadIdx.x + o];
        __syncthreads();
    }
    if (threadIdx.x == 0) g_partial[blockIdx.x] = red[0];
}

__global__ void reduce2_kernel(float* __restrict__ out, int nblocks, float scale) {
    __shared__ float red[128];
    float s = 0.0f;
    for (int i = threadIdx.x; i < nblocks; i += 128) s += g_partial[i];
    red[threadIdx.x] = s;
    __syncthreads();
    for (int o = 64; o > 0; o >>= 1) {
        if (threadIdx.x < o) red[threadIdx.x] += red[threadIdx.x + o];
        __syncthreads();
    }
    if (threadIdx.x == 0) out[0] = red[0] * scale;
}

extern "C" void kernel_launch(void* const* d_in, const int* in_sizes, int n_in,
                              void* d_out, int out_size) {
    const float* pred = (const float*)d_in[0];
    const float* targ = (const float*)d_in[1];
    int B = in_sizes[0] / (N_PTS * 3);              // b*s = 16

    dim3 grid(STRIPS, B, 2 * CS);                    // 8 x 16 x 16 = 2048 blocks
    nn_min_kernel<<<grid, THREADS>>>(pred, targ);

    int nrows = 2 * B * N_PTS;                       // 131072
    reduce1_kernel<<<128, 256>>>(nrows);
    reduce2_kernel<<<1, 128>>>((float*)d_out, 128, 1.0f / ((float)B * (float)N_PTS));
}